// round 1
// baseline (speedup 1.0000x reference)
#include <cuda_runtime.h>
#include <cuda_bf16.h>
#include <math.h>

#define BB 4
#define CC 64
#define OO 64
#define HH 128
#define WW 128
#define KK 9
#define OFFCH 27

// scratch for offset-conv output: [B][27][H][W]
__device__ float g_off[(size_t)BB * OFFCH * HH * WW];

// ---------------------------------------------------------------------------
// Kernel 1: regular 3x3 conv, 64 -> 27 channels, pad 1, + bias.
// Block = (b, h) row; 128 threads = one per w. Weights in SMEM [c*9+ki][28].
// ---------------------------------------------------------------------------
__global__ void __launch_bounds__(128) offset_conv_kernel(
    const float* __restrict__ x,
    const float* __restrict__ w_off,
    const float* __restrict__ b_off)
{
    extern __shared__ float sm1[];
    float* wsh = sm1;                     // [576][28]
    float* xs  = sm1 + 576 * 28;          // [3][132]

    const int h = blockIdx.x;
    const int b = blockIdx.y;
    const int w = threadIdx.x;

    // load weights: w_off global layout [27][64][3][3] -> wsh[(c*9+ki)*28 + o]
    for (int i = threadIdx.x; i < OFFCH * 576; i += 128) {
        int o  = i / 576;
        int ck = i % 576;
        wsh[ck * 28 + o] = w_off[i];
    }
    for (int i = threadIdx.x; i < 576; i += 128) wsh[i * 28 + 27] = 0.0f;

    float acc[28];
#pragma unroll
    for (int o = 0; o < 27; o++) acc[o] = b_off[o];
    acc[27] = 0.0f;

    const float* xb = x + (size_t)b * CC * HH * WW;

    for (int c = 0; c < CC; c++) {
        __syncthreads();
        // stage rows h-1..h+1 of channel c, cols -1..128 (zero padded)
        const float* xc = xb + (size_t)c * HH * WW;
        for (int i = threadIdx.x; i < 3 * 130; i += 128) {
            int r   = i / 130;
            int col = i % 130;
            int y   = h - 1 + r;
            int xx  = col - 1;
            float v = 0.0f;
            if (y >= 0 && y < HH && xx >= 0 && xx < WW) v = xc[y * WW + xx];
            xs[r * 132 + col] = v;
        }
        __syncthreads();

#pragma unroll
        for (int r = 0; r < 3; r++) {
#pragma unroll
            for (int dx = 0; dx < 3; dx++) {
                float xv = xs[r * 132 + w + dx];
                const float4* wp = (const float4*)(wsh + (c * 9 + r * 3 + dx) * 28);
#pragma unroll
                for (int q = 0; q < 7; q++) {
                    float4 ww = wp[q];
                    acc[q * 4 + 0] += ww.x * xv;
                    acc[q * 4 + 1] += ww.y * xv;
                    acc[q * 4 + 2] += ww.z * xv;
                    acc[q * 4 + 3] += ww.w * xv;
                }
            }
        }
    }

#pragma unroll
    for (int o = 0; o < 27; o++) {
        g_off[(((size_t)b * OFFCH + o) * HH + h) * WW + w] = acc[o];
    }
}

// ---------------------------------------------------------------------------
// Kernel 2: deformable sampling + main conv + BN + ReLU.
// Block = (b, h) row; 256 threads = 128 pixels x 2 O-halves (32 each).
// Weights in SMEM [c*9+k][64]. Per-pixel tap geometry precomputed once.
// ---------------------------------------------------------------------------
__global__ void __launch_bounds__(256) dcn_bn_relu_kernel(
    const float* __restrict__ x,
    const float* __restrict__ weight,
    const float* __restrict__ bias,
    const float* __restrict__ gamma,
    const float* __restrict__ beta,
    const float* __restrict__ rmean,
    const float* __restrict__ rvar,
    float* __restrict__ out)
{
    extern __shared__ float sm2[];
    float* wsh    = sm2;                 // [576][64]
    float* bscale = sm2 + 576 * 64;      // [64]
    float* bshift = bscale + 64;         // [64]

    const int h  = blockIdx.x;
    const int b  = blockIdx.y;
    const int w  = threadIdx.x & 127;
    const int oh = threadIdx.x >> 7;     // 0 or 1: which half of O

    // weight global [64][64][3][3] -> wsh[(c*9+k)*64 + o]
    for (int i = threadIdx.x; i < OO * 576; i += 256) {
        int o  = i / 576;
        int ck = i % 576;
        wsh[ck * 64 + o] = weight[i];
    }
    if (threadIdx.x < 64) {
        int o = threadIdx.x;
        float sc = gamma[o] * rsqrtf(rvar[o] + 1e-5f);
        bscale[o] = sc;
        bshift[o] = (bias[o] - rmean[o]) * sc + beta[o];
    }
    __syncthreads();

    // per-pixel tap geometry
    const float* offp = g_off + ((size_t)b * OFFCH * HH + h) * WW + w; // ch stride HH*WW
    const int chs = HH * WW;

    int   ofs[9][4];
    float cf[9][4];
#pragma unroll
    for (int k = 0; k < 9; k++) {
        float oy = offp[(2 * k) * chs];
        float ox = offp[(2 * k + 1) * chs];
        float mr = offp[(18 + k) * chs];
        float m  = 1.0f / (1.0f + __expf(-mr));

        float py = (float)h + (float)(k / 3 - 1) + oy;
        float px = (float)w + (float)(k % 3 - 1) + ox;
        float y0f = floorf(py), x0f = floorf(px);
        float dy = py - y0f, dx = px - x0f;
        int y0 = (int)y0f, x0 = (int)x0f;
        int y1 = y0 + 1,   x1 = x0 + 1;
        bool vy0 = (y0 >= 0) && (y0 < HH), vy1 = (y1 >= 0) && (y1 < HH);
        bool vx0 = (x0 >= 0) && (x0 < WW), vx1 = (x1 >= 0) && (x1 < WW);
        int cy0 = min(max(y0, 0), HH - 1), cy1 = min(max(y1, 0), HH - 1);
        int cx0 = min(max(x0, 0), WW - 1), cx1 = min(max(x1, 0), WW - 1);

        ofs[k][0] = cy0 * WW + cx0;  cf[k][0] = (vy0 && vx0) ? (1.0f - dy) * (1.0f - dx) * m : 0.0f;
        ofs[k][1] = cy0 * WW + cx1;  cf[k][1] = (vy0 && vx1) ? (1.0f - dy) * dx * m        : 0.0f;
        ofs[k][2] = cy1 * WW + cx0;  cf[k][2] = (vy1 && vx0) ? dy * (1.0f - dx) * m        : 0.0f;
        ofs[k][3] = cy1 * WW + cx1;  cf[k][3] = (vy1 && vx1) ? dy * dx * m                 : 0.0f;
    }

    float acc[32];
#pragma unroll
    for (int o = 0; o < 32; o++) acc[o] = 0.0f;

    const float* xb = x + (size_t)b * CC * HH * WW;

    for (int c = 0; c < CC; c++) {
        const float* xc = xb + (size_t)c * chs;
        float val[9];
#pragma unroll
        for (int k = 0; k < 9; k++) {
            val[k] = cf[k][0] * __ldg(xc + ofs[k][0])
                   + cf[k][1] * __ldg(xc + ofs[k][1])
                   + cf[k][2] * __ldg(xc + ofs[k][2])
                   + cf[k][3] * __ldg(xc + ofs[k][3]);
        }
        const float* wrow = wsh + c * 9 * 64 + oh * 32;
#pragma unroll
        for (int k = 0; k < 9; k++) {
            const float4* wp = (const float4*)(wrow + k * 64);
            float v = val[k];
#pragma unroll
            for (int q = 0; q < 8; q++) {
                float4 ww = wp[q];
                acc[q * 4 + 0] += ww.x * v;
                acc[q * 4 + 1] += ww.y * v;
                acc[q * 4 + 2] += ww.z * v;
                acc[q * 4 + 3] += ww.w * v;
            }
        }
    }

    float* op = out + (((size_t)b * OO + oh * 32) * HH + h) * WW + w;
#pragma unroll
    for (int o = 0; o < 32; o++) {
        float v = acc[o] * bscale[oh * 32 + o] + bshift[oh * 32 + o];
        op[o * chs] = fmaxf(v, 0.0f);
    }
}

// ---------------------------------------------------------------------------

extern "C" void kernel_launch(void* const* d_in, const int* in_sizes, int n_in,
                              void* d_out, int out_size)
{
    const float* x      = (const float*)d_in[0];
    const float* w_off  = (const float*)d_in[1];
    const float* b_off  = (const float*)d_in[2];
    const float* weight = (const float*)d_in[3];
    const float* bias   = (const float*)d_in[4];
    const float* gamma  = (const float*)d_in[5];
    const float* beta   = (const float*)d_in[6];
    const float* rmean  = (const float*)d_in[7];
    const float* rvar   = (const float*)d_in[8];
    float* out = (float*)d_out;

    const int smem1 = (576 * 28 + 3 * 132) * sizeof(float);           // ~66 KB
    const int smem2 = (576 * 64 + 128) * sizeof(float);               // ~148 KB

    cudaFuncSetAttribute(offset_conv_kernel,
                         cudaFuncAttributeMaxDynamicSharedMemorySize, smem1);
    cudaFuncSetAttribute(dcn_bn_relu_kernel,
                         cudaFuncAttributeMaxDynamicSharedMemorySize, smem2);

    dim3 grid(HH, BB);
    offset_conv_kernel<<<grid, 128, smem1>>>(x, w_off, b_off);
    dcn_bn_relu_kernel<<<grid, 256, smem2>>>(x, weight, bias, gamma, beta,
                                             rmean, rvar, out);
}

// round 2
// speedup vs baseline: 1.9807x; 1.9807x over previous
#include <cuda_runtime.h>
#include <cuda_bf16.h>
#include <math.h>

#define BB 4
#define CC 64
#define OO 64
#define HH 128
#define WW 128
#define CHS (HH * WW)

// padded SMEM row widths (floats)
#define WPAD 68     // main weight row: 64 outputs padded to 68 (4-way max bank conflict on store)
#define OPAD 28     // offset weight row: 27 padded to 28

// -------- packed f32x2 helpers --------
__device__ __forceinline__ unsigned long long pack2(float lo, float hi) {
    unsigned long long r;
    asm("mov.b64 %0, {%1, %2};" : "=l"(r) : "f"(lo), "f"(hi));
    return r;
}
__device__ __forceinline__ void unpack2(unsigned long long v, float& lo, float& hi) {
    asm("mov.b64 {%0, %1}, %2;" : "=f"(lo), "=f"(hi) : "l"(v));
}
__device__ __forceinline__ unsigned long long ffma2(unsigned long long a,
                                                    unsigned long long b,
                                                    unsigned long long c) {
    unsigned long long d;
    asm("fma.rn.f32x2 %0, %1, %2, %3;" : "=l"(d) : "l"(a), "l"(b), "l"(c));
    return d;
}

// ---------------------------------------------------------------------------
// Fused: offset-conv -> geometry -> modulated deformable conv -> BN -> ReLU.
// Block = 2 image rows (256 threads, 1 thread per pixel).
// SMEM: main weight [c*9+k][68], offset weight [c*9+k][28], BN scale/shift.
// ---------------------------------------------------------------------------
__global__ void __launch_bounds__(256, 1) dcn_fused_kernel(
    const float* __restrict__ x,
    const float* __restrict__ w_off,
    const float* __restrict__ b_off,
    const float* __restrict__ weight,
    const float* __restrict__ gamma_bias_etc_unused, // placeholder (not used)
    const float* __restrict__ bias,
    const float* __restrict__ gamma,
    const float* __restrict__ beta,
    const float* __restrict__ rmean,
    const float* __restrict__ rvar,
    float* __restrict__ out)
{
    extern __shared__ float sm[];
    float* wsh    = sm;                       // [576][WPAD]
    float* wosh   = sm + 576 * WPAD;          // [576][OPAD]
    float* bscale = wosh + 576 * OPAD;        // [64]
    float* bshift = bscale + 64;              // [64]

    const int tid = threadIdx.x;
    const int hh  = tid >> 7;                  // 0/1: which row of the pair
    const int w   = tid & 127;
    const int gr  = blockIdx.x * 2 + hh;       // global row 0..511
    const int b   = gr >> 7;
    const int h   = gr & 127;

    // ---- stage main weights: global [o][c*9+k] -> smem [c*9+k][WPAD] ----
    for (int i = tid; i < OO * 576; i += 256) {
        int o  = i / 576;
        int ck = i % 576;
        wsh[ck * WPAD + o] = weight[i];
    }
    // ---- stage offset weights: global [oc][c*9+k] -> smem [c*9+k][OPAD] ----
    for (int i = tid; i < 27 * 576; i += 256) {
        int oc = i / 576;
        int ck = i % 576;
        wosh[ck * OPAD + oc] = w_off[i];
    }
    for (int i = tid; i < 576; i += 256) wosh[i * OPAD + 27] = 0.0f;
    // ---- BN constants ----
    if (tid < 64) {
        int o = tid;
        float sc = gamma[o] * rsqrtf(rvar[o] + 1e-5f);
        bscale[o] = sc;
        bshift[o] = (bias[o] - rmean[o]) * sc + beta[o];
    }
    __syncthreads();

    const float* xb = x + (size_t)b * CC * CHS;

    // =======================================================================
    // Phase 1: offset conv (regular 3x3, 64 -> 27+1 channels), packed f32x2
    // =======================================================================
    int  p1o[9];
    bool p1v[9];
#pragma unroll
    for (int k = 0; k < 9; k++) {
        int y  = h + k / 3 - 1;
        int xx = w + k % 3 - 1;
        p1v[k] = (y >= 0) & (y < HH) & (xx >= 0) & (xx < WW);
        p1o[k] = y * WW + xx;
    }

    unsigned long long offa[14];
#pragma unroll
    for (int j = 0; j < 13; j++) offa[j] = pack2(b_off[2 * j], b_off[2 * j + 1]);
    offa[13] = pack2(b_off[26], 0.0f);

    for (int c = 0; c < CC; c++) {
        const float* xc = xb + c * CHS;
        float xv[9];
#pragma unroll
        for (int k = 0; k < 9; k++)
            xv[k] = p1v[k] ? __ldg(xc + p1o[k]) : 0.0f;

#pragma unroll
        for (int k = 0; k < 9; k++) {
            unsigned long long v2 = pack2(xv[k], xv[k]);
            const ulonglong2* wp = (const ulonglong2*)(wosh + (c * 9 + k) * OPAD);
#pragma unroll
            for (int q = 0; q < 7; q++) {
                ulonglong2 ww = wp[q];
                offa[2 * q]     = ffma2(ww.x, v2, offa[2 * q]);
                offa[2 * q + 1] = ffma2(ww.y, v2, offa[2 * q + 1]);
            }
        }
    }

    float offv[28];
#pragma unroll
    for (int j = 0; j < 14; j++) unpack2(offa[j], offv[2 * j], offv[2 * j + 1]);

    // =======================================================================
    // Geometry: per-tap bilinear corners + coefficients (mask folded in)
    // =======================================================================
    int   ofs[9][4];
    float cf[9][4];
#pragma unroll
    for (int k = 0; k < 9; k++) {
        float oy = offv[2 * k];
        float ox = offv[2 * k + 1];
        float m  = 1.0f / (1.0f + __expf(-offv[18 + k]));

        float py = (float)(h + k / 3 - 1) + oy;
        float px = (float)(w + k % 3 - 1) + ox;
        float y0f = floorf(py), x0f = floorf(px);
        float dy = py - y0f, dx = px - x0f;
        int y0 = (int)y0f, x0 = (int)x0f;
        int y1 = y0 + 1,   x1 = x0 + 1;
        bool vy0 = (y0 >= 0) & (y0 < HH), vy1 = (y1 >= 0) & (y1 < HH);
        bool vx0 = (x0 >= 0) & (x0 < WW), vx1 = (x1 >= 0) & (x1 < WW);
        int cy0 = min(max(y0, 0), HH - 1), cy1 = min(max(y1, 0), HH - 1);
        int cx0 = min(max(x0, 0), WW - 1), cx1 = min(max(x1, 0), WW - 1);

        ofs[k][0] = cy0 * WW + cx0;  cf[k][0] = (vy0 && vx0) ? (1.0f - dy) * (1.0f - dx) * m : 0.0f;
        ofs[k][1] = cy0 * WW + cx1;  cf[k][1] = (vy0 && vx1) ? (1.0f - dy) * dx * m          : 0.0f;
        ofs[k][2] = cy1 * WW + cx0;  cf[k][2] = (vy1 && vx0) ? dy * (1.0f - dx) * m          : 0.0f;
        ofs[k][3] = cy1 * WW + cx1;  cf[k][3] = (vy1 && vx1) ? dy * dx * m                   : 0.0f;
    }

    // =======================================================================
    // Phase 2: modulated deformable conv, packed f32x2 accumulation
    // =======================================================================
    unsigned long long acc[32];
#pragma unroll
    for (int j = 0; j < 32; j++) acc[j] = 0ULL;

    for (int c = 0; c < CC; c++) {
        const float* xc = xb + c * CHS;
        float val[9];
#pragma unroll
        for (int k = 0; k < 9; k++) {
            val[k] = cf[k][0] * __ldg(xc + ofs[k][0])
                   + cf[k][1] * __ldg(xc + ofs[k][1])
                   + cf[k][2] * __ldg(xc + ofs[k][2])
                   + cf[k][3] * __ldg(xc + ofs[k][3]);
        }
#pragma unroll
        for (int k = 0; k < 9; k++) {
            unsigned long long v2 = pack2(val[k], val[k]);
            const ulonglong2* wp = (const ulonglong2*)(wsh + (c * 9 + k) * WPAD);
#pragma unroll
            for (int q = 0; q < 16; q++) {
                ulonglong2 ww = wp[q];
                acc[2 * q]     = ffma2(ww.x, v2, acc[2 * q]);
                acc[2 * q + 1] = ffma2(ww.y, v2, acc[2 * q + 1]);
            }
        }
    }

    // =======================================================================
    // BN + ReLU + store (NCHW)
    // =======================================================================
    float* op = out + ((size_t)b * OO * HH + h) * WW + w;
#pragma unroll
    for (int j = 0; j < 32; j++) {
        float lo, hi;
        unpack2(acc[j], lo, hi);
        int o0 = 2 * j, o1 = 2 * j + 1;
        float r0 = fmaxf(lo * bscale[o0] + bshift[o0], 0.0f);
        float r1 = fmaxf(hi * bscale[o1] + bshift[o1], 0.0f);
        op[(size_t)o0 * CHS] = r0;
        op[(size_t)o1 * CHS] = r1;
    }
}

// ---------------------------------------------------------------------------

extern "C" void kernel_launch(void* const* d_in, const int* in_sizes, int n_in,
                              void* d_out, int out_size)
{
    const float* x      = (const float*)d_in[0];
    const float* w_off  = (const float*)d_in[1];
    const float* b_off  = (const float*)d_in[2];
    const float* weight = (const float*)d_in[3];
    const float* bias   = (const float*)d_in[4];
    const float* gamma  = (const float*)d_in[5];
    const float* beta   = (const float*)d_in[6];
    const float* rmean  = (const float*)d_in[7];
    const float* rvar   = (const float*)d_in[8];
    float* out = (float*)d_out;

    const int smem = (576 * WPAD + 576 * OPAD + 128) * sizeof(float); // ~217 KB

    cudaFuncSetAttribute(dcn_fused_kernel,
                         cudaFuncAttributeMaxDynamicSharedMemorySize, smem);

    dcn_fused_kernel<<<BB * HH / 2, 256, smem>>>(
        x, w_off, b_off, weight, nullptr, bias, gamma, beta, rmean, rvar, out);
}